// round 17
// baseline (speedup 1.0000x reference)
#include <cuda_runtime.h>
#include <cuda_bf16.h>
#include <math.h>
#include <stdint.h>

typedef __nv_bfloat16 bf16;

#define BB 2
#define SS 1024
#define DD 1024
#define HH 16
#define LL 3
#define FFF 4096
#define VV 32000
#define MTOK (BB*SS)
#define NQKV 3072

// ------------------------- scratch -------------------------
__device__ float g_h[MTOK * DD];
__device__ float g_t2[2 * MTOK * DD];
__device__ float g_bqkv[LL * NQKV];

__device__ bf16 s_h[2 * MTOK * DD];
__device__ bf16 s_qkv[2 * MTOK * NQKV];
__device__ bf16 s_attn[2 * MTOK * DD];
__device__ bf16 s_t1[2 * MTOK * FFF];

__device__ bf16 s_wqkv[2 * LL * DD * NQKV];
__device__ bf16 s_wo[2 * LL * DD * DD];
__device__ bf16 s_w1[2 * LL * DD * FFF];
__device__ bf16 s_w2[2 * LL * FFF * DD];
__device__ bf16 s_wout[2 * DD * VV];

// ------------------------- helpers -------------------------
__device__ __forceinline__ uint32_t pack_hi2(float x, float y) {
    __nv_bfloat162 v = __halves2bfloat162(__float2bfloat16_rn(x), __float2bfloat16_rn(y));
    return *reinterpret_cast<uint32_t*>(&v);
}
__device__ __forceinline__ uint32_t pack_lo2(float x, float y) {
    float rx = x - __bfloat162float(__float2bfloat16_rn(x));
    float ry = y - __bfloat162float(__float2bfloat16_rn(y));
    __nv_bfloat162 v = __halves2bfloat162(__float2bfloat16_rn(rx), __float2bfloat16_rn(ry));
    return *reinterpret_cast<uint32_t*>(&v);
}
__device__ __forceinline__ uint32_t cvta_smem(const void* p) {
    return (uint32_t)__cvta_generic_to_shared(p);
}
__device__ __forceinline__ void cp16(uint32_t dst, const void* src) {
    asm volatile("cp.async.cg.shared.global [%0], [%1], 16;" :: "r"(dst), "l"(src) : "memory");
}
__device__ __forceinline__ void cp_commit() { asm volatile("cp.async.commit_group;" ::: "memory"); }
__device__ __forceinline__ void cp_wait0()  { asm volatile("cp.async.wait_group 0;" ::: "memory"); }
__device__ __forceinline__ void cp_wait1()  { asm volatile("cp.async.wait_group 1;" ::: "memory"); }
__device__ __forceinline__ void ldm4(uint32_t* r, uint32_t a) {
    asm volatile("ldmatrix.sync.aligned.m8n8.x4.shared.b16 {%0,%1,%2,%3}, [%4];"
                 : "=r"(r[0]), "=r"(r[1]), "=r"(r[2]), "=r"(r[3]) : "r"(a));
}
__device__ __forceinline__ void ldm4t(uint32_t* r, uint32_t a) {
    asm volatile("ldmatrix.sync.aligned.m8n8.x4.trans.shared.b16 {%0,%1,%2,%3}, [%4];"
                 : "=r"(r[0]), "=r"(r[1]), "=r"(r[2]), "=r"(r[3]) : "r"(a));
}
#define MMA_BF16(c, a, b)                                                     \
    asm volatile("mma.sync.aligned.m16n8k16.row.col.f32.bf16.bf16.f32 "       \
                 "{%0,%1,%2,%3}, {%4,%5,%6,%7}, {%8,%9}, {%0,%1,%2,%3};"      \
                 : "+f"(c[0]), "+f"(c[1]), "+f"(c[2]), "+f"(c[3])             \
                 : "r"(a[0]), "r"(a[1]), "r"(a[2]), "r"(a[3]),                \
                   "r"(b[0]), "r"(b[1]))

// ------------------------- split kernels (16 elem/thread, MLP=4) -----------
__global__ void split_kernel(const float* __restrict__ in, bf16* __restrict__ out, int n)
{
    int i16 = (blockIdx.x * blockDim.x + threadIdx.x) * 16;
    if (i16 >= n) return;
    float4 a0 = *(const float4*)(in + i16);
    float4 a1 = *(const float4*)(in + i16 + 4);
    float4 a2 = *(const float4*)(in + i16 + 8);
    float4 a3 = *(const float4*)(in + i16 + 12);
    uint4 h0 = {pack_hi2(a0.x,a0.y), pack_hi2(a0.z,a0.w), pack_hi2(a1.x,a1.y), pack_hi2(a1.z,a1.w)};
    uint4 h1 = {pack_hi2(a2.x,a2.y), pack_hi2(a2.z,a2.w), pack_hi2(a3.x,a3.y), pack_hi2(a3.z,a3.w)};
    uint4 l0 = {pack_lo2(a0.x,a0.y), pack_lo2(a0.z,a0.w), pack_lo2(a1.x,a1.y), pack_lo2(a1.z,a1.w)};
    uint4 l1 = {pack_lo2(a2.x,a2.y), pack_lo2(a2.z,a2.w), pack_lo2(a3.x,a3.y), pack_lo2(a3.z,a3.w)};
    *(uint4*)(out + i16)         = h0;
    *(uint4*)(out + i16 + 8)     = h1;
    *(uint4*)(out + n + i16)     = l0;
    *(uint4*)(out + n + i16 + 8) = l1;
}

// merged QKV split + bias concat: y=0/1/2 -> Wq/Wk/Wv planes, y=3 -> bias
__global__ void split_qkv(const float* __restrict__ Wq, const float* __restrict__ Wk,
                          const float* __restrict__ Wv, bf16* __restrict__ oh,
                          bf16* __restrict__ ol,
                          const float* __restrict__ bq, const float* __restrict__ bk,
                          const float* __restrict__ bv, float* __restrict__ bout)
{
    int t = blockIdx.y;
    if (t == 3) {
        int i = blockIdx.x * blockDim.x + threadIdx.x;
        if (i >= LL * NQKV) return;
        int l = i / NQKV, j = i % NQKV;
        float v = (j < DD) ? bq[l*DD + j] : (j < 2*DD) ? bk[l*DD + j - DD] : bv[l*DD + j - 2*DD];
        bout[i] = v;
        return;
    }
    const float* in = (t == 0) ? Wq : (t == 1) ? Wk : Wv;
    int i16 = (blockIdx.x * blockDim.x + threadIdx.x) * 16;
    if (i16 >= DD * DD) return;
    int row = i16 / DD, col = i16 % DD;
    size_t o = (size_t)row * NQKV + t * DD + col;
    float4 a0 = *(const float4*)(in + i16);
    float4 a1 = *(const float4*)(in + i16 + 4);
    float4 a2 = *(const float4*)(in + i16 + 8);
    float4 a3 = *(const float4*)(in + i16 + 12);
    uint4 h0 = {pack_hi2(a0.x,a0.y), pack_hi2(a0.z,a0.w), pack_hi2(a1.x,a1.y), pack_hi2(a1.z,a1.w)};
    uint4 h1 = {pack_hi2(a2.x,a2.y), pack_hi2(a2.z,a2.w), pack_hi2(a3.x,a3.y), pack_hi2(a3.z,a3.w)};
    uint4 l0 = {pack_lo2(a0.x,a0.y), pack_lo2(a0.z,a0.w), pack_lo2(a1.x,a1.y), pack_lo2(a1.z,a1.w)};
    uint4 l1 = {pack_lo2(a2.x,a2.y), pack_lo2(a2.z,a2.w), pack_lo2(a3.x,a3.y), pack_lo2(a3.z,a3.w)};
    *(uint4*)(oh + o)     = h0;
    *(uint4*)(oh + o + 8) = h1;
    *(uint4*)(ol + o)     = l0;
    *(uint4*)(ol + o + 8) = l1;
}

// ------------------------- embedding -------------------------
__global__ void embed_kernel(const int* __restrict__ x, const float* __restrict__ noise,
                             const float* __restrict__ emb, float* __restrict__ h,
                             bf16* __restrict__ sh)
{
    int i4 = (blockIdx.x * blockDim.x + threadIdx.x) * 4;
    int tok = i4 >> 10, d = i4 & 1023;
    float4 e = *(const float4*)(emb + (size_t)x[tok] * DD + d);
    float4 nz = *(const float4*)(noise + i4);
    float4 v = {e.x + 0.05f*nz.x, e.y + 0.05f*nz.y, e.z + 0.05f*nz.z, e.w + 0.05f*nz.w};
    *(float4*)(h + i4) = v;
    *(uint32_t*)(sh + i4)                 = pack_hi2(v.x, v.y);
    *(uint32_t*)(sh + i4 + 2)             = pack_hi2(v.z, v.w);
    *(uint32_t*)(sh + MTOK*DD + i4)       = pack_lo2(v.x, v.y);
    *(uint32_t*)(sh + MTOK*DD + i4 + 2)   = pack_lo2(v.z, v.w);
}

// ============================================================================
// Fused attention (FA2-style) with phase-pipelined K/V loads.
// ============================================================================
__global__ __launch_bounds__(256, 2)
void attn_fused(const bf16* __restrict__ QKVh, const bf16* __restrict__ QKVl,
                bf16* __restrict__ Ohi, bf16* __restrict__ Olo)
{
    extern __shared__ __align__(16) unsigned char smem[];
    const uint32_t s0 = cvta_smem(smem);
    const uint32_t QH = s0, QL = s0 + 16384;
    const uint32_t KH = s0 + 32768, KL = s0 + 49152;
    const uint32_t VH = s0 + 65536, VL = s0 + 81920;

    const int tid = threadIdx.x;
    const int lane = tid & 31, wid = tid >> 5;
    const int q8 = lane >> 3, r8 = lane & 7;
    const int grp = lane >> 2, qp = (lane & 3) << 1;
    const int qblk = blockIdx.x;
    const int z = blockIdx.y;
    const int b = z >> 4, hd = z & 15;

    const bf16* Qh = QKVh + (size_t)b * SS * NQKV + hd * 64;
    const bf16* Ql = QKVl + (size_t)b * SS * NQKV + hd * 64;
    const bf16* Kh = Qh + DD;
    const bf16* Kl = Ql + DD;
    const bf16* Vh = Qh + 2 * DD;
    const bf16* Vl = Ql + 2 * DD;

    const int ldrow = tid >> 1, ldc = tid & 1;

    auto load_K = [&](int kt) {
#pragma unroll
        for (int p = 0; p < 4; p++) {
            size_t g = (size_t)(kt * 128 + ldrow) * NQKV + p * 16 + ldc * 8;
            uint32_t off = p * 4096 + ldrow * 32 + ((ldc ^ ((ldrow >> 2) & 1)) << 4);
            cp16(KH + off, Kh + g);
            cp16(KL + off, Kl + g);
        }
        cp_commit();
    };
    auto load_V = [&](int kt) {
        for (int t = tid; t < 1024; t += 256) {
            int krow = t >> 3, cc = t & 7;
            size_t g = (size_t)(kt * 128 + krow) * NQKV + cc * 8;
            uint32_t off = krow * 128 + ((cc ^ (krow & 7)) << 4);
            cp16(VH + off, Vh + g);
            cp16(VL + off, Vl + g);
        }
        cp_commit();
    };

    {
#pragma unroll
        for (int p = 0; p < 4; p++) {
            size_t g = (size_t)(qblk * 128 + ldrow) * NQKV + p * 16 + ldc * 8;
            uint32_t off = p * 4096 + ldrow * 32 + ((ldc ^ ((ldrow >> 2) & 1)) << 4);
            cp16(QH + off, Qh + g);
            cp16(QL + off, Ql + g);
        }
        cp_commit();
    }
    load_K(0);
    load_V(0);

    float o_acc[8][4] = {};
    float dsum0 = 0.f, dsum1 = 0.f;

    const int arow = wid * 16 + ((q8 & 1) << 3) + r8;
    const int ac = q8 >> 1;

    auto s_phase = [&](int half, float s_acc[8][4]) {
#pragma unroll
        for (int kp = 0; kp < 4; kp++) {
            uint32_t aoff = kp * 4096 + arow * 32 + ((ac ^ ((arow >> 2) & 1)) << 4);
            uint32_t ah[4], al[4];
            ldm4(ah, QH + aoff);
            ldm4(al, QL + aoff);
#pragma unroll
            for (int jj = 0; jj < 4; jj++) {
                int krow = half * 64 + jj * 16 + ((q8 & 1) << 3) + r8;
                uint32_t boff = kp * 4096 + krow * 32 + ((ac ^ ((krow >> 2) & 1)) << 4);
                uint32_t rh[4], rl[4];
                ldm4(rh, KH + boff);
                ldm4(rl, KL + boff);
                uint32_t b0h[2] = {rh[0], rh[2]}, b1h[2] = {rh[1], rh[3]};
                uint32_t b0l[2] = {rl[0], rl[2]}, b1l[2] = {rl[1], rl[3]};
                MMA_BF16(s_acc[2*jj], ah, b0h);
                MMA_BF16(s_acc[2*jj], ah, b0l);
                MMA_BF16(s_acc[2*jj], al, b0h);
                MMA_BF16(s_acc[2*jj+1], ah, b1h);
                MMA_BF16(s_acc[2*jj+1], ah, b1l);
                MMA_BF16(s_acc[2*jj+1], al, b1h);
            }
        }
    };
    auto exp_pack = [&](float s_acc[8][4], uint32_t pAh[4][4], uint32_t pAl[4][4]) {
#pragma unroll
        for (int kk = 0; kk < 4; kk++) {
            float e0 = __expf(s_acc[2*kk][0] * 0.125f);
            float e1 = __expf(s_acc[2*kk][1] * 0.125f);
            float e2 = __expf(s_acc[2*kk][2] * 0.125f);
            float e3 = __expf(s_acc[2*kk][3] * 0.125f);
            float f0 = __expf(s_acc[2*kk+1][0] * 0.125f);
            float f1 = __expf(s_acc[2*kk+1][1] * 0.125f);
            float f2 = __expf(s_acc[2*kk+1][2] * 0.125f);
            float f3 = __expf(s_acc[2*kk+1][3] * 0.125f);
            dsum0 += e0 + e1 + f0 + f1;
            dsum1 += e2 + e3 + f2 + f3;
            pAh[kk][0] = pack_hi2(e0, e1); pAh[kk][1] = pack_hi2(e2, e3);
            pAh[kk][2] = pack_hi2(f0, f1); pAh[kk][3] = pack_hi2(f2, f3);
            pAl[kk][0] = pack_lo2(e0, e1); pAl[kk][1] = pack_lo2(e2, e3);
            pAl[kk][2] = pack_lo2(f0, f1); pAl[kk][3] = pack_lo2(f2, f3);
        }
    };
    auto pv_phase = [&](int half, uint32_t pAh[4][4], uint32_t pAl[4][4]) {
#pragma unroll
        for (int kk = 0; kk < 4; kk++) {
            int vkrow = half * 64 + kk * 16 + ((q8 & 1) << 3) + r8;
#pragma unroll
            for (int jj = 0; jj < 4; jj++) {
                int cc = jj * 2 + (q8 >> 1);
                uint32_t voff = vkrow * 128 + ((cc ^ (vkrow & 7)) << 4);
                uint32_t rh[4], rl[4];
                ldm4t(rh, VH + voff);
                ldm4t(rl, VL + voff);
                uint32_t v0h[2] = {rh[0], rh[1]}, v1h[2] = {rh[2], rh[3]};
                uint32_t v0l[2] = {rl[0], rl[1]}, v1l[2] = {rl[2], rl[3]};
                MMA_BF16(o_acc[2*jj], pAh[kk], v0h);
                MMA_BF16(o_acc[2*jj], pAh[kk], v0l);
                MMA_BF16(o_acc[2*jj], pAl[kk], v0h);
                MMA_BF16(o_acc[2*jj+1], pAh[kk], v1h);
                MMA_BF16(o_acc[2*jj+1], pAh[kk], v1l);
                MMA_BF16(o_acc[2*jj+1], pAl[kk], v1h);
            }
        }
    };

    for (int kt = 0; kt < 8; kt++) {
        cp_wait1();
        __syncthreads();

        float s_acc0[8][4] = {};
        s_phase(0, s_acc0);
        uint32_t pAh0[4][4], pAl0[4][4];
        exp_pack(s_acc0, pAh0, pAl0);

        cp_wait0();
        __syncthreads();
        pv_phase(0, pAh0, pAl0);

        float s_acc1[8][4] = {};
        s_phase(1, s_acc1);
        uint32_t pAh1[4][4], pAl1[4][4];
        exp_pack(s_acc1, pAh1, pAl1);

        __syncthreads();
        if (kt + 1 < 8) load_K(kt + 1);

        pv_phase(1, pAh1, pAl1);

        __syncthreads();
        if (kt + 1 < 8) load_V(kt + 1);
    }

    dsum0 += __shfl_xor_sync(0xffffffffu, dsum0, 1);
    dsum0 += __shfl_xor_sync(0xffffffffu, dsum0, 2);
    dsum1 += __shfl_xor_sync(0xffffffffu, dsum1, 1);
    dsum1 += __shfl_xor_sync(0xffffffffu, dsum1, 2);
    float inv0 = 1.0f / dsum0, inv1 = 1.0f / dsum1;

    int gr = b * SS + qblk * 128 + wid * 16 + grp;
#pragma unroll
    for (int j = 0; j < 8; j++) {
        int col = hd * 64 + j * 8 + qp;
        float v00 = o_acc[j][0] * inv0, v01 = o_acc[j][1] * inv0;
        float v10 = o_acc[j][2] * inv1, v11 = o_acc[j][3] * inv1;
        size_t o0 = (size_t)gr * DD + col;
        size_t o1 = (size_t)(gr + 8) * DD + col;
        *(uint32_t*)(Ohi + o0) = pack_hi2(v00, v01);
        *(uint32_t*)(Olo + o0) = pack_lo2(v00, v01);
        *(uint32_t*)(Ohi + o1) = pack_hi2(v10, v11);
        *(uint32_t*)(Olo + o1) = pack_lo2(v10, v11);
    }
}

// ------------------------- tensor-core split GEMM, BK=32, 3-stage ----------
template<int BM, int BN, int WARPS_M, int WARPS_N, int SWAP>
__global__ __launch_bounds__(256, 2)
void gemm_tc(const bf16* __restrict__ Ahi, const bf16* __restrict__ Alo, int lda,
             long sAb, long sAh,
             const bf16* __restrict__ Bhi, const bf16* __restrict__ Blo, int ldb,
             long sBb, long sBh,
             float* __restrict__ Cf, bf16* __restrict__ Chi, bf16* __restrict__ Clo,
             int ldc, long sCb, long sCh,
             const float* __restrict__ bias, float alpha, int relu, int K)
{
    constexpr int WTM = BM / WARPS_M, WTN = BN / WARPS_N;
    constexpr int IT = WTM / 16, JT = WTN / 8;
    constexpr int BP16 = 16 * BN * 2;
    constexpr int A_SZ = 16384;
    constexpr int STAGE = A_SZ + 4 * BP16;

    extern __shared__ __align__(16) unsigned char smem[];

    const int tid = threadIdx.x;
    const int lane = tid & 31, wid = tid >> 5;
    const int wm = wid / WARPS_N, wn = wid % WARPS_N;
    const int bm = (SWAP ? blockIdx.x : blockIdx.y) * BM;
    const int bn = (SWAP ? blockIdx.y : blockIdx.x) * BN;
    const int z = blockIdx.z, zb = z >> 4, zh = z & 15;

    const bf16* gAh = Ahi + (size_t)zb * sAb + (size_t)zh * sAh;
    const bf16* gAl = Alo + (size_t)zb * sAb + (size_t)zh * sAh;
    const bf16* gBh = Bhi + (size_t)zb * sBb + (size_t)zh * sBh;
    const bf16* gBl = Blo + (size_t)zb * sBb + (size_t)zh * sBh;
    const uint32_t s0 = cvta_smem(smem);

    float acc[IT][JT][4] = {};
    const int KT = K / 32;

    auto load_stage = [&](int kt, int st) {
        uint32_t base = s0 + st * STAGE;
        {
            int m = tid >> 1, c = tid & 1;
            uint32_t aoff = m * 32 + ((c ^ ((m >> 2) & 1)) << 4);
#pragma unroll
            for (int p = 0; p < 2; p++) {
                size_t g = (size_t)(bm + m) * lda + kt * 32 + p * 16 + c * 8;
                cp16(base + p * 8192 + aoff, gAh + g);
                cp16(base + p * 8192 + 4096 + aoff, gAl + g);
            }
        }
        {
            constexpr int CPR = BN / 8;
            if (16 * CPR == 256 || tid < 16 * CPR) {
                int k = tid / CPR, c = tid % CPR;
                uint32_t boff = k * (BN * 2) + ((c ^ (k & 7)) << 4);
#pragma unroll
                for (int p = 0; p < 2; p++) {
                    size_t g = (size_t)(kt * 32 + p * 16 + k) * ldb + bn + c * 8;
                    cp16(base + A_SZ + p * 2 * BP16 + boff, gBh + g);
                    cp16(base + A_SZ + p * 2 * BP16 + BP16 + boff, gBl + g);
                }
            }
        }
        cp_commit();
    };

    load_stage(0, 0);
    if (KT > 1) load_stage(1, 1);
    const int q8 = lane >> 3, r8 = lane & 7;

    int st_idx = 0;
    for (int kt = 0; kt < KT; kt++) {
        if (kt + 1 < KT) cp_wait1(); else cp_wait0();
        __syncthreads();
        if (kt + 2 < KT) {
            int nst = st_idx + 2; if (nst >= 3) nst -= 3;
            load_stage(kt + 2, nst);
        }

        uint32_t st = s0 + st_idx * STAGE;
        if (++st_idx == 3) st_idx = 0;
#pragma unroll
        for (int ksl = 0; ksl < 2; ksl++) {
            uint32_t sa_hi = st + ksl * 8192;
            uint32_t sa_lo = sa_hi + 4096;
            uint32_t sb_hi = st + A_SZ + ksl * 2 * BP16;
            uint32_t sb_lo = sb_hi + BP16;

            uint32_t ah[IT][4], al[IT][4];
#pragma unroll
            for (int i = 0; i < IT; i++) {
                int rrow = wm * WTM + i * 16 + ((q8 & 1) << 3) + r8;
                int c = q8 >> 1;
                uint32_t off = rrow * 32 + ((c ^ ((rrow >> 2) & 1)) << 4);
                ldm4(ah[i], sa_hi + off);
                ldm4(al[i], sa_lo + off);
            }
#pragma unroll
            for (int jj = 0; jj < JT / 2; jj++) {
                int krow = ((q8 & 1) << 3) + r8;
                int c = (wn * WTN + jj * 16) / 8 + (q8 >> 1);
                uint32_t off = krow * (BN * 2) + ((c ^ (krow & 7)) << 4);
                uint32_t rh[4], rl[4];
                ldm4t(rh, sb_hi + off);
                ldm4t(rl, sb_lo + off);
                uint32_t b0h[2] = {rh[0], rh[1]}, b1h[2] = {rh[2], rh[3]};
                uint32_t b0l[2] = {rl[0], rl[1]}, b1l[2] = {rl[2], rl[3]};
#pragma unroll
                for (int i = 0; i < IT; i++) {
                    MMA_BF16(acc[i][2*jj], ah[i], b0h);
                    MMA_BF16(acc[i][2*jj], ah[i], b0l);
                    MMA_BF16(acc[i][2*jj], al[i], b0h);
                    MMA_BF16(acc[i][2*jj+1], ah[i], b1h);
                    MMA_BF16(acc[i][2*jj+1], ah[i], b1l);
                    MMA_BF16(acc[i][2*jj+1], al[i], b1h);
                }
            }
        }
    }

    float* pCf = Cf ? Cf + (size_t)zb * sCb + (size_t)zh * sCh : (float*)0;
    bf16* pChi = Chi ? Chi + (size_t)zb * sCb + (size_t)zh * sCh : (bf16*)0;
    bf16* pClo = Clo ? Clo + (size_t)zb * sCb + (size_t)zh * sCh : (bf16*)0;
    const int grp = lane >> 2, qp = (lane & 3) << 1;
#pragma unroll
    for (int i = 0; i < IT; i++) {
        int r0 = bm + wm * WTM + i * 16 + grp;
#pragma unroll
        for (int j = 0; j < JT; j++) {
            int n0 = bn + wn * WTN + j * 8 + qp;
            float b0 = 0.f, b1 = 0.f;
            if (bias) { b0 = __ldg(bias + n0); b1 = __ldg(bias + n0 + 1); }
            float v00 = (acc[i][j][0] + b0) * alpha;
            float v01 = (acc[i][j][1] + b1) * alpha;
            float v10 = (acc[i][j][2] + b0) * alpha;
            float v11 = (acc[i][j][3] + b1) * alpha;
            if (relu) {
                v00 = fmaxf(v00, 0.f); v01 = fmaxf(v01, 0.f);
                v10 = fmaxf(v10, 0.f); v11 = fmaxf(v11, 0.f);
            }
            size_t o0 = (size_t)r0 * ldc + n0;
            size_t o1 = (size_t)(r0 + 8) * ldc + n0;
            if (pCf) {
                float2 a = {v00, v01}, b = {v10, v11};
                *(float2*)(pCf + o0) = a;
                *(float2*)(pCf + o1) = b;
            }
            if (pChi) {
                *(uint32_t*)(pChi + o0) = pack_hi2(v00, v01);
                *(uint32_t*)(pClo + o0) = pack_lo2(v00, v01);
                *(uint32_t*)(pChi + o1) = pack_hi2(v10, v11);
                *(uint32_t*)(pClo + o1) = pack_lo2(v10, v11);
            }
        }
    }
}

// --------- residual + LayerNorm over two split-K partials (+bias, +split) ---
__global__ void add_ln3(float* __restrict__ h, const float* __restrict__ p1,
                        const float* __restrict__ p2, const float* __restrict__ bias,
                        const float* __restrict__ g, const float* __restrict__ be,
                        bf16* __restrict__ sh)
{
    float* hr = h + (size_t)blockIdx.x * DD;
    const float* y1 = p1 + (size_t)blockIdx.x * DD;
    const float* y2 = p2 + (size_t)blockIdx.x * DD;
    const int tid = threadIdx.x;
    __shared__ float red[8];

    float4 hv = *(float4*)(hr + tid * 4);
    float4 a1 = *(const float4*)(y1 + tid * 4);
    float4 a2 = *(const float4*)(y2 + tid * 4);
    float4 bb = *(const float4*)(bias + tid * 4);
    float z[4] = {hv.x + a1.x + a2.x + bb.x, hv.y + a1.y + a2.y + bb.y,
                  hv.z + a1.z + a2.z + bb.z, hv.w + a1.w + a2.w + bb.w};

    float s = z[0] + z[1] + z[2] + z[3];
#pragma unroll
    for (int o = 16; o; o >>= 1) s += __shfl_xor_sync(0xffffffffu, s, o);
    if ((tid & 31) == 0) red[tid >> 5] = s;
    __syncthreads();
    float tot = 0.f;
#pragma unroll
    for (int i = 0; i < 8; i++) tot += red[i];
    float mean = tot * (1.0f / DD);
    __syncthreads();

    float d0 = z[0]-mean, d1 = z[1]-mean, d2 = z[2]-mean, d3 = z[3]-mean;
    float vs = d0*d0 + d1*d1 + d2*d2 + d3*d3;
#pragma unroll
    for (int o = 16; o; o >>= 1) vs += __shfl_xor_sync(0xffffffffu, vs, o);
    if ((tid & 31) == 0) red[tid >> 5] = vs;
    __syncthreads();
    float vtot = 0.f;
#pragma unroll
    for (int i = 0; i < 8; i++) vtot += red[i];
    float rstd = rsqrtf(vtot * (1.0f / DD) + 1e-5f);

    float4 gv = *(const float4*)(g + tid * 4);
    float4 bv = *(const float4*)(be + tid * 4);
    float4 o;
    o.x = d0*rstd*gv.x + bv.x; o.y = d1*rstd*gv.y + bv.y;
    o.z = d2*rstd*gv.z + bv.z; o.w = d3*rstd*gv.w + bv.w;
    *(float4*)(hr + tid * 4) = o;

    size_t ob = (size_t)blockIdx.x * DD + tid * 4;
    *(uint32_t*)(sh + ob)               = pack_hi2(o.x, o.y);
    *(uint32_t*)(sh + ob + 2)           = pack_hi2(o.z, o.w);
    *(uint32_t*)(sh + MTOK*DD + ob)     = pack_lo2(o.x, o.y);
    *(uint32_t*)(sh + MTOK*DD + ob + 2) = pack_lo2(o.z, o.w);
}

// ------------------------- launch -------------------------
extern "C" void kernel_launch(void* const* d_in, const int* in_sizes, int n_in,
                              void* d_out, int out_size)
{
    const int*   x     = (const int*)d_in[0];
    const float* noise = (const float*)d_in[1];
    const float* emb   = (const float*)d_in[2];
    const float* Wq    = (const float*)d_in[3];
    const float* bq    = (const float*)d_in[4];
    const float* Wk    = (const float*)d_in[5];
    const float* bk    = (const float*)d_in[6];
    const float* Wv    = (const float*)d_in[7];
    const float* bv    = (const float*)d_in[8];
    const float* Wo    = (const float*)d_in[9];
    const float* bo    = (const float*)d_in[10];
    const float* W1f   = (const float*)d_in[11];
    const float* b1f   = (const float*)d_in[12];
    const float* W2f   = (const float*)d_in[13];
    const float* b2f   = (const float*)d_in[14];
    const float* g1    = (const float*)d_in[15];
    const float* be1   = (const float*)d_in[16];
    const float* g2    = (const float*)d_in[17];
    const float* be2   = (const float*)d_in[18];
    const float* Wout  = (const float*)d_in[19];
    const float* bout  = (const float*)d_in[20];
    float* out = (float*)d_out;

    float *h, *t2, *bqkv;
    bf16 *sh, *sqkv, *sat, *st1;
    bf16 *wqkv, *wo, *w1, *w2, *wout;
    cudaGetSymbolAddress((void**)&h, g_h);
    cudaGetSymbolAddress((void**)&t2, g_t2);
    cudaGetSymbolAddress((void**)&bqkv, g_bqkv);
    cudaGetSymbolAddress((void**)&sh, s_h);
    cudaGetSymbolAddress((void**)&sqkv, s_qkv);
    cudaGetSymbolAddress((void**)&sat, s_attn);
    cudaGetSymbolAddress((void**)&st1, s_t1);
    cudaGetSymbolAddress((void**)&wqkv, s_wqkv);
    cudaGetSymbolAddress((void**)&wo, s_wo);
    cudaGetSymbolAddress((void**)&w1, s_w1);
    cudaGetSymbolAddress((void**)&w2, s_w2);
    cudaGetSymbolAddress((void**)&wout, s_wout);

    cudaFuncSetAttribute((const void*)gemm_tc<128,128,2,4,1>,
                         cudaFuncAttributeMaxDynamicSharedMemorySize, 98304);
    cudaFuncSetAttribute((const void*)attn_fused,
                         cudaFuncAttributeMaxDynamicSharedMemorySize, 98304);

    const int nQ = LL * DD * DD;
    const int nF = LL * DD * FFF;
    const int nO = DD * VV;
    const long WQKV_PLANE = (long)LL * DD * NQKV;
    const long HD = (long)MTOK * DD;
    const long QP = (long)MTOK * NQKV;
    const long TF = (long)MTOK * FFF;

    // layer-0 QKV split (16 elem/thread) + bias concat; embed
    split_qkv<<<dim3(DD*DD/4096, 4), 256>>>(Wq, Wk, Wv, wqkv, wqkv + WQKV_PLANE,
                                            bq, bk, bv, bqkv);
    embed_kernel<<<(MTOK * DD) / 1024, 256>>>(x, noise, emb, h, sh);

    // layer-0 fused QKV GEMM; attn_fused (ncu window)
    gemm_tc<128,128,2,4,1><<<dim3(16, NQKV/128, 1), 256, 98304>>>(
        sh, sh+HD, DD, 0,0, wqkv, wqkv + WQKV_PLANE, NQKV, 0,0,
        (float*)0, sqkv, sqkv+QP, NQKV, 0,0, bqkv, 1.f, 0, DD);

    attn_fused<<<dim3(SS/128, BB*HH), 256, 98304>>>(
        sqkv, sqkv+QP, sat, sat+HD);

    for (int l = 1; l < LL; l++) {
        bf16* oh = wqkv + (size_t)l * DD * NQKV;
        split_qkv<<<dim3(DD*DD/4096, 3), 256>>>(
            Wq + (size_t)l*DD*DD, Wk + (size_t)l*DD*DD, Wv + (size_t)l*DD*DD,
            oh, oh + WQKV_PLANE, bq, bk, bv, bqkv);
    }
    split_kernel<<<nQ/4096, 256>>>(Wo, wo, nQ);
    split_kernel<<<nF/4096, 256>>>(W1f, w1, nF);
    split_kernel<<<nF/4096, 256>>>(W2f, w2, nF);
    split_kernel<<<nO/4096, 256>>>(Wout, wout, nO);

    for (int i = 0; i < LL; i++) {
        const bf16 *wqkvh = wqkv + (size_t)i * DD * NQKV, *wqkvl = wqkvh + WQKV_PLANE;
        const bf16 *woh = wo + (size_t)i * DD * DD, *wol = woh + nQ;
        const bf16 *w1h = w1 + (size_t)i * DD * FFF, *w1l = w1h + nF;
        const bf16 *w2h = w2 + (size_t)i * FFF * DD, *w2l = w2h + nF;

        if (i > 0) {
            gemm_tc<128,128,2,4,1><<<dim3(16, NQKV/128, 1), 256, 98304>>>(
                sh, sh+HD, DD, 0,0, wqkvh, wqkvl, NQKV, 0,0,
                (float*)0, sqkv, sqkv+QP, NQKV, 0,0, bqkv + i*NQKV, 1.f, 0, DD);
            attn_fused<<<dim3(SS/128, BB*HH), 256, 98304>>>(
                sqkv, sqkv+QP, sat, sat+HD);
        }

        gemm_tc<128,128,2,4,1><<<dim3(16,8,2), 256, 98304>>>(
            sat, sat+HD, DD, 0, 512, woh, wol, DD, 0, (long)512*DD,
            t2, (bf16*)0, (bf16*)0, DD, 0, HD, (float*)0, 1.f, 0, 512);
        add_ln3<<<MTOK, 256>>>(h, t2, t2 + HD, bo + i*DD, g1 + i*DD, be1 + i*DD, sh);

        gemm_tc<128,128,2,4,1><<<dim3(16,32,1), 256, 98304>>>(
            sh, sh+HD, DD, 0,0, w1h, w1l, FFF, 0,0,
            (float*)0, st1, st1+TF, FFF, 0,0, b1f + i*FFF, 1.f, 1, DD);

        gemm_tc<128,128,2,4,1><<<dim3(16,8,2), 256, 98304>>>(
            st1, st1+TF, FFF, 0, 2048, w2h, w2l, DD, 0, (long)2048*DD,
            t2, (bf16*)0, (bf16*)0, DD, 0, HD, (float*)0, 1.f, 0, 2048);
        add_ln3<<<MTOK, 256>>>(h, t2, t2 + HD, b2f + i*DD, g2 + i*DD, be2 + i*DD, sh);
    }

    gemm_tc<128,128,2,4,1><<<dim3(16, VV/128, 1), 256, 98304>>>(
        sh, sh+HD, DD, 0,0, wout, wout + nO, VV, 0,0,
        out, (bf16*)0, (bf16*)0, VV, 0,0, bout, 1.f, 0, DD);
}